// round 4
// baseline (speedup 1.0000x reference)
#include <cuda_runtime.h>
#include <math.h>

#define NJ 33
#define FD 256
#define MAXB 4096
#define NNMAX (MAXB*NJ)
#define MAXE 165
#define ST 36            // transposed tile row stride (floats); rows 0..35

typedef unsigned long long u64;

// ---- scratch (no allocations allowed) ----
__device__ float g_bufA[(size_t)NNMAX*FD];
__device__ float g_bufB[(size_t)NNMAX*FD];
__device__ float g_sum[FD], g_sumsq[FD];
__device__ float g_scale[FD], g_shift[FD];
__device__ int   g_rp[NJ+1];
__device__ int   g_ci[MAXE];
__device__ float g_av[MAXE];
__device__ float g_acol[NJ];
__device__ float g_whc[FD*4];
__device__ float g_bhc[4];

// ============================================================
// Prep: normalized adjacency CSR (identical for every graph),
// pooled column weights a_col, fused classifier whc = wh@wc.
// ============================================================
__global__ void prep_kernel(const int* __restrict__ src, const int* __restrict__ dst,
                            int epg,
                            const float* __restrict__ wh, const float* __restrict__ wc,
                            const float* __restrict__ bh, const float* __restrict__ bc) {
    __shared__ float s_dinv[NJ];
    int tid = threadIdx.x;
    if (tid < NJ) {
        int d = 0;
        for (int e = 0; e < epg; ++e) d += (dst[e] == tid);
        s_dinv[tid] = rsqrtf((float)d);
    }
    if (tid < FD) { g_sum[tid] = 0.f; g_sumsq[tid] = 0.f; }
    __syncthreads();
    if (tid == 0) {
        int pos = 0;
        for (int j = 0; j < NJ; ++j) {
            g_rp[j] = pos;
            for (int e = 0; e < epg && pos < MAXE; ++e) {
                if (dst[e] == j) {
                    int r = src[e];
                    g_ci[pos] = r;
                    g_av[pos] = s_dinv[r] * s_dinv[j];
                    pos++;
                }
            }
        }
        g_rp[NJ] = pos;
    }
    if (tid < NJ) {
        float s = 0.f;
        for (int e = 0; e < epg; ++e)
            if (src[e] == tid) s += s_dinv[tid] * s_dinv[dst[e]];
        g_acol[tid] = s / (float)NJ;
    }
    for (int idx = tid; idx < FD*4; idx += blockDim.x) {
        int k = idx >> 2, l = idx & 3;
        float s = 0.f;
        for (int c = 0; c < FD; ++c) s += wh[k*FD + c] * wc[c*4 + l];
        g_whc[idx] = s;
    }
    if (tid < 4) {
        float s = 0.f;
        for (int c = 0; c < FD; ++c) s += bh[c] * wc[c*4 + tid];
        g_bhc[tid] = s + bc[tid];
    }
}

// ============================================================
// Fused GCN layer, packed-fp32 (fma.rn.f32x2) GEMM.
// One block per graph. 256 threads = 128 column-pairs x 2 halves.
//   cp   = tid & 127 : owns output columns {2cp, 2cp+1}
//   half = tid >> 7  : row-pairs over rows [0,18) or [18,36) (rows >=33 = pad 0)
// Input tile stored TRANSPOSED: shT[k*ST + r], so packed (row,row+1)
// operands come straight from LDS.64/128; weights dup-packed per k.
// ============================================================
__global__ void __launch_bounds__(256)
layer_kernel(const float* __restrict__ in_ext,
             const float* __restrict__ W,
             const float* __restrict__ bias,
             int mode /*0 = nan_to_num, 1 = BN+relu*/,
             int in_sel, int out_sel) {
    __shared__ float sh[256*ST];         // 36864B: transposed input, then reused for y
    __shared__ int   s_rp[NJ+1];
    __shared__ int   s_ci[MAXE];
    __shared__ float s_av[MAXE];

    const int tid  = threadIdx.x;
    const int cp   = tid & 127;
    const int half = tid >> 7;
    const int rbase = half ? 18 : 0;
    const int b    = blockIdx.x;

    const float* in = (in_sel == 1) ? g_bufA : (in_sel == 2) ? g_bufB : in_ext;
    float*      out = (out_sel == 1) ? g_bufA : g_bufB;
    const float* inb = in + (size_t)b * NJ * FD;

    float sc = 1.f, shf = 0.f;
    if (mode == 1) { sc = g_scale[tid]; shf = g_shift[tid]; }

    // Load input (coalesced: channel == tid), store transposed.
    #pragma unroll
    for (int r = 0; r < NJ; ++r) {
        float v = inb[r*FD + tid];
        if (mode == 0) { if (v != v) v = 0.f; }
        else           { v = fmaxf(fmaf(v, sc, shf), 0.f); }
        sh[tid*ST + r] = v;
    }
    sh[tid*ST + 33] = 0.f; sh[tid*ST + 34] = 0.f; sh[tid*ST + 35] = 0.f;
    if (tid <= NJ) s_rp[tid] = g_rp[tid];
    if (tid < MAXE) { s_ci[tid] = g_ci[tid]; s_av[tid] = g_av[tid]; }
    __syncthreads();

    // GEMM: packed accs acc[i][c] = (y[r0][c], y[r1][c]), r0 = rbase+2i.
    u64 acc[9][2];
    #pragma unroll
    for (int i = 0; i < 9; ++i) { acc[i][0] = 0ull; acc[i][1] = 0ull; }

    const float2* __restrict__ W2 = (const float2*)W;

    #pragma unroll 2
    for (int k = 0; k < FD; ++k) {
        const float2 w = W2[k*(FD/2) + cp];
        u64 wdx, wdy;
        asm("mov.b64 %0, {%1, %1};" : "=l"(wdx) : "f"(w.x));
        asm("mov.b64 %0, {%1, %1};" : "=l"(wdy) : "f"(w.y));

        const float* hk = &sh[k*ST + rbase];
        u64 h[9];
        if (half == 0) {
            // rows 0..17: 4x LDS.128 + 1x LDS.64 (all 16B/8B aligned: k*36 ≡ 0 mod 4)
            #pragma unroll
            for (int q = 0; q < 4; ++q) {
                ulonglong2 v = *(const ulonglong2*)(hk + 4*q);
                h[2*q] = v.x; h[2*q+1] = v.y;
            }
            h[8] = *(const u64*)(hk + 16);
        } else {
            // rows 18..35: LDS.64 @18, 4x LDS.128 @20,24,28,32 (abs addr 16B aligned)
            h[0] = *(const u64*)(hk);
            #pragma unroll
            for (int q = 0; q < 4; ++q) {
                ulonglong2 v = *(const ulonglong2*)(hk + 2 + 4*q);
                h[2*q+1] = v.x; h[2*q+2] = v.y;
            }
        }
        #pragma unroll
        for (int i = 0; i < 9; ++i) {
            asm("fma.rn.f32x2 %0, %1, %2, %0;" : "+l"(acc[i][0]) : "l"(h[i]), "l"(wdx));
            asm("fma.rn.f32x2 %0, %1, %2, %0;" : "+l"(acc[i][1]) : "l"(h[i]), "l"(wdy));
        }
    }

    // Stage y back in standard layout y[r][c] (reuse sh), for sparse gather.
    __syncthreads();
    float2* ysh = (float2*)sh;           // [r*128 + cp]
    #pragma unroll
    for (int i = 0; i < 9; ++i) {
        const int r0 = rbase + 2*i, r1 = r0 + 1;
        const float2 a0 = *(const float2*)&acc[i][0];  // (y[r0][c0], y[r1][c0])
        const float2 a1 = *(const float2*)&acc[i][1];
        if (r0 < NJ) ysh[r0*128 + cp] = make_float2(a0.x, a1.x);
        if (r1 < NJ) ysh[r1*128 + cp] = make_float2(a0.y, a1.y);
    }
    __syncthreads();

    // Sparse epilogue: half0 owns j=0..16, half1 j=17..32; BN sums via atomics.
    const float2 bia = ((const float2*)bias)[cp];
    float2 s1 = make_float2(0.f, 0.f), s2 = make_float2(0.f, 0.f);
    float* outb = out + (size_t)b * NJ * FD;

    const int jlo = half ? 17 : 0;
    const int jhi = half ? 33 : 17;
    for (int j = jlo; j < jhi; ++j) {
        float zx = bia.x, zy = bia.y;
        const int p0 = s_rp[j], p1 = s_rp[j+1];
        for (int p = p0; p < p1; ++p) {
            const int   r = s_ci[p];
            const float a = s_av[p];
            const float2 y = ysh[r*128 + cp];
            zx = fmaf(a, y.x, zx);
            zy = fmaf(a, y.y, zy);
        }
        ((float2*)outb)[j*128 + cp] = make_float2(zx, zy);
        s1.x += zx; s1.y += zy;
        s2.x = fmaf(zx, zx, s2.x); s2.y = fmaf(zy, zy, s2.y);
    }
    atomicAdd(&g_sum[2*cp],       s1.x);
    atomicAdd(&g_sum[2*cp + 1],   s1.y);
    atomicAdd(&g_sumsq[2*cp],     s2.x);
    atomicAdd(&g_sumsq[2*cp + 1], s2.y);
}

// ============================================================
__global__ void stats_kernel(const float* __restrict__ g, const float* __restrict__ be,
                             float inv_nn) {
    int tid = threadIdx.x;
    float mu  = g_sum[tid] * inv_nn;
    float var = g_sumsq[tid] * inv_nn - mu * mu;
    float rs  = rsqrtf(var + 1e-5f);
    float sc  = rs * g[tid];
    g_scale[tid] = sc;
    g_shift[tid] = be[tid] - mu * sc;
    g_sum[tid] = 0.f; g_sumsq[tid] = 0.f;
}

// ============================================================
// Final fused layer: BN2+ReLU -> a_col^T h -> @ (wh@wc) + bhc
// ============================================================
__global__ void __launch_bounds__(256)
final_kernel(float* __restrict__ out) {
    __shared__ float s_acol[NJ];
    __shared__ float s_red[8][4];
    const int tid = threadIdx.x;
    const int b   = blockIdx.x;
    if (tid < NJ) s_acol[tid] = g_acol[tid];
    __syncthreads();

    const float sc  = g_scale[tid];
    const float shf = g_shift[tid];
    const float* inb = g_bufA + (size_t)b * NJ * FD;

    float v = 0.f;
    #pragma unroll
    for (int r = 0; r < NJ; ++r) {
        float x = inb[r*FD + tid];
        x = fmaxf(fmaf(x, sc, shf), 0.f);
        v = fmaf(s_acol[r], x, v);
    }
    float4 w = ((const float4*)g_whc)[tid];
    float p0 = v * w.x, p1 = v * w.y, p2 = v * w.z, p3 = v * w.w;
    #pragma unroll
    for (int o = 16; o; o >>= 1) {
        p0 += __shfl_down_sync(0xffffffffu, p0, o);
        p1 += __shfl_down_sync(0xffffffffu, p1, o);
        p2 += __shfl_down_sync(0xffffffffu, p2, o);
        p3 += __shfl_down_sync(0xffffffffu, p3, o);
    }
    const int lane = tid & 31, wid = tid >> 5;
    if (lane == 0) { s_red[wid][0] = p0; s_red[wid][1] = p1; s_red[wid][2] = p2; s_red[wid][3] = p3; }
    __syncthreads();
    if (tid < 4) {
        float s = 0.f;
        #pragma unroll
        for (int w8 = 0; w8 < 8; ++w8) s += s_red[w8][tid];
        out[b*4 + tid] = s + g_bhc[tid];
    }
}

// ============================================================
extern "C" void kernel_launch(void* const* d_in, const int* in_sizes, int n_in,
                              void* d_out, int out_size) {
    const float* x   = (const float*)d_in[0];
    const float* w0  = (const float*)d_in[1];
    const float* b0  = (const float*)d_in[2];
    const float* gg0 = (const float*)d_in[3];
    const float* be0 = (const float*)d_in[4];
    const float* w1  = (const float*)d_in[5];
    const float* b1  = (const float*)d_in[6];
    const float* gg1 = (const float*)d_in[7];
    const float* be1 = (const float*)d_in[8];
    const float* w2  = (const float*)d_in[9];
    const float* b2  = (const float*)d_in[10];
    const float* gg2 = (const float*)d_in[11];
    const float* be2 = (const float*)d_in[12];
    const float* wh  = (const float*)d_in[13];
    const float* bh  = (const float*)d_in[14];
    const float* wc  = (const float*)d_in[15];
    const float* bc  = (const float*)d_in[16];
    const int*   src = (const int*)d_in[17];
    const int*   dst = (const int*)d_in[18];
    float* out = (float*)d_out;

    const int B   = in_sizes[0] / (NJ * FD);
    const int epg = in_sizes[17] / B;
    const float inv_nn = 1.0f / (float)(B * NJ);

    prep_kernel<<<1, 256>>>(src, dst, epg, wh, wc, bh, bc);

    layer_kernel<<<B, 256>>>(x, w0, b0, /*mode=*/0, /*in_sel=*/0, /*out_sel=*/1);
    stats_kernel<<<1, 256>>>(gg0, be0, inv_nn);
    layer_kernel<<<B, 256>>>(nullptr, w1, b1, 1, 1, 2);
    stats_kernel<<<1, 256>>>(gg1, be1, inv_nn);
    layer_kernel<<<B, 256>>>(nullptr, w2, b2, 1, 2, 1);
    stats_kernel<<<1, 256>>>(gg2, be2, inv_nn);
    final_kernel<<<B, 256>>>(out);
}

// round 7
// speedup vs baseline: 1.8528x; 1.8528x over previous
#include <cuda_runtime.h>
#include <cuda_bf16.h>
#include <math.h>
#include <stdint.h>

#define NJ 33
#define FD 256
#define MAXB 4096
#define NNMAX (MAXB*NJ)
#define MAXE 165

typedef uint32_t u32;
typedef uint64_t u64;

// ---- scratch (no allocations allowed) ----
__device__ float g_bufA[(size_t)NNMAX*FD];
__device__ float g_bufB[(size_t)NNMAX*FD];
__device__ float g_sum[FD], g_sumsq[FD];
__device__ float g_scale[FD], g_shift[FD];
__device__ int   g_rp[NJ+1];
__device__ int   g_ci[MAXE];
__device__ float g_av[MAXE];
__device__ float g_acol[NJ];
__device__ float g_whc[FD*4];
__device__ float g_bhc[4];
// Weights pre-packed in m16n8k16 B-fragment order, bf16 hi/lo split.
// Index: (nf*16 + ks)*32 + lane ; nf = n/8 (32), ks = k/16 (16), lane 0..31.
// u64 = {b0 = (W[k][n],W[k+1][n]), b1 = (W[k+8][n],W[k+9][n])}, k = ks*16+(lane%4)*2, n = nf*8+lane/4.
__device__ u64 g_wb_hi[3][16384];
__device__ u64 g_wb_lo[3][16384];

// ============================================================
// Prep: CSR of normalized adjacency (shared by all graphs),
// a_col pooling weights, fused head whc = wh@wc.
// ============================================================
__global__ void prep_kernel(const int* __restrict__ src, const int* __restrict__ dst,
                            int epg,
                            const float* __restrict__ wh, const float* __restrict__ wc,
                            const float* __restrict__ bh, const float* __restrict__ bc) {
    __shared__ float s_dinv[NJ];
    int tid = threadIdx.x;
    if (tid < NJ) {
        int d = 0;
        for (int e = 0; e < epg; ++e) d += (dst[e] == tid);
        s_dinv[tid] = rsqrtf((float)d);
    }
    if (tid < FD) { g_sum[tid] = 0.f; g_sumsq[tid] = 0.f; }
    __syncthreads();
    if (tid == 0) {
        int pos = 0;
        for (int j = 0; j < NJ; ++j) {
            g_rp[j] = pos;
            for (int e = 0; e < epg && pos < MAXE; ++e) {
                if (dst[e] == j) {
                    int r = src[e];
                    g_ci[pos] = r;
                    g_av[pos] = s_dinv[r] * s_dinv[j];
                    pos++;
                }
            }
        }
        g_rp[NJ] = pos;
    }
    if (tid < NJ) {
        float s = 0.f;
        for (int e = 0; e < epg; ++e)
            if (src[e] == tid) s += s_dinv[tid] * s_dinv[dst[e]];
        g_acol[tid] = s / (float)NJ;
    }
    for (int idx = tid; idx < FD*4; idx += blockDim.x) {
        int k = idx >> 2, l = idx & 3;
        float s = 0.f;
        for (int c = 0; c < FD; ++c) s += wh[k*FD + c] * wc[c*4 + l];
        g_whc[idx] = s;
    }
    if (tid < 4) {
        float s = 0.f;
        for (int c = 0; c < FD; ++c) s += bh[c] * wc[c*4 + tid];
        g_bhc[tid] = s + bc[tid];
    }
}

// W[k][n] fp32 -> fragment-ordered bf16 hi/lo pack.
__global__ void convw_kernel(const float* __restrict__ W, int layer) {
    const int i = blockIdx.x * 256 + threadIdx.x;       // 0..16383
    const int lane = i & 31;
    const int ks = (i >> 5) & 15;
    const int nf = i >> 9;
    const int n = nf*8 + (lane >> 2);
    const int k = ks*16 + (lane & 3)*2;
    float e0 = W[k*FD + n],     e1 = W[(k+1)*FD + n];
    float e2 = W[(k+8)*FD + n], e3 = W[(k+9)*FD + n];
    __nv_bfloat162 h0 = __floats2bfloat162_rn(e0, e1);
    __nv_bfloat162 h1 = __floats2bfloat162_rn(e2, e3);
    __nv_bfloat162 l0 = __floats2bfloat162_rn(e0 - __low2float(h0), e1 - __high2float(h0));
    __nv_bfloat162 l1 = __floats2bfloat162_rn(e2 - __low2float(h1), e3 - __high2float(h1));
    g_wb_hi[layer][i] = (u64)(*(u32*)&h0) | ((u64)(*(u32*)&h1) << 32);
    g_wb_lo[layer][i] = (u64)(*(u32*)&l0) | ((u64)(*(u32*)&l1) << 32);
}

// ============================================================
// Pass A: Y = pre(Z) @ W via mma.sync m16n8k16 bf16 (3-term split).
// Block tile 128x256, 8 warps = 2m x 4n, warp tile 64x64.
// K chunked by 128 through smem (A hi/lo bf16, 272B row stride).
// ============================================================
#define SM_HI 0
#define SM_LO 34816
#define SM_SC 69632
#define SM_SH 70656
#define GEMM_SMEM 71680
#define ASTRIDE 272     // bytes per A smem row (256 data + 16 pad)

__device__ __forceinline__ void mma16816(float* d, u32 a0, u32 a1, u32 a2, u32 a3,
                                         u32 b0, u32 b1) {
    asm volatile(
        "mma.sync.aligned.m16n8k16.row.col.f32.bf16.bf16.f32 "
        "{%0,%1,%2,%3}, {%4,%5,%6,%7}, {%8,%9}, {%0,%1,%2,%3};"
        : "+f"(d[0]), "+f"(d[1]), "+f"(d[2]), "+f"(d[3])
        : "r"(a0), "r"(a1), "r"(a2), "r"(a3), "r"(b0), "r"(b1));
}

__global__ void __launch_bounds__(256)
gemm_kernel(const float* __restrict__ x_ext, int mode, int layer, int Bn, int NN) {
    extern __shared__ char smem[];
    const int tid  = threadIdx.x;
    const int lane = tid & 31, wid = tid >> 5;
    const int wm = wid & 1, wn = wid >> 1;
    const int m0 = blockIdx.x * 128;

    // scale/shift to smem (used in mode 1)
    *(float*)(smem + SM_SC + tid*4) = g_scale[tid];
    *(float*)(smem + SM_SH + tid*4) = g_shift[tid];

    float acc[4][8][4];
    #pragma unroll
    for (int mf = 0; mf < 4; ++mf)
        #pragma unroll
        for (int nf = 0; nf < 8; ++nf)
            #pragma unroll
            for (int q = 0; q < 4; ++q) acc[mf][nf][q] = 0.f;

    const u64* __restrict__ WBH = g_wb_hi[layer];
    const u64* __restrict__ WBL = g_wb_lo[layer];

    // loader mapping: row = tid>>1, half = tid&1 (64 cols each)
    const int rowl = tid >> 1, halfc = tid & 1;
    const int m_ld = m0 + rowl;
    const float* srcrow;
    if (mode == 0) {
        const int j = m_ld / Bn, g = m_ld - j*Bn;
        srcrow = x_ext + ((size_t)g*NJ + j)*FD;
    } else {
        srcrow = g_bufA + (size_t)m_ld*FD;
    }
    const bool vld = (m_ld < NN);
    char* hib = smem + SM_HI + rowl*ASTRIDE + halfc*128;
    char* lob = smem + SM_LO + rowl*ASTRIDE + halfc*128;
    const float* ssc = (const float*)(smem + SM_SC);
    const float* ssh = (const float*)(smem + SM_SH);

    // fragment smem byte offsets (per thread)
    const int arow = wm*64 + (lane >> 2);
    const int acol = (lane & 3)*4;               // bytes within k16 step

    for (int c = 0; c < 2; ++c) {
        __syncthreads();                          // smem reusable (also covers sc/sh copy)
        // ---- stage A chunk: rows 0..127, k in [c*128, c*128+128) ----
        #pragma unroll
        for (int i = 0; i < 16; ++i) {
            const int k = c*128 + halfc*64 + i*4;
            float4 v = make_float4(0.f, 0.f, 0.f, 0.f);
            if (vld) v = *(const float4*)(srcrow + k);
            if (mode == 0) {
                if (v.x != v.x) v.x = 0.f;
                if (v.y != v.y) v.y = 0.f;
                if (v.z != v.z) v.z = 0.f;
                if (v.w != v.w) v.w = 0.f;
            } else {
                v.x = fmaxf(fmaf(v.x, ssc[k],   ssh[k]),   0.f);
                v.y = fmaxf(fmaf(v.y, ssc[k+1], ssh[k+1]), 0.f);
                v.z = fmaxf(fmaf(v.z, ssc[k+2], ssh[k+2]), 0.f);
                v.w = fmaxf(fmaf(v.w, ssc[k+3], ssh[k+3]), 0.f);
            }
            __nv_bfloat162 h0 = __floats2bfloat162_rn(v.x, v.y);
            __nv_bfloat162 h1 = __floats2bfloat162_rn(v.z, v.w);
            __nv_bfloat162 l0 = __floats2bfloat162_rn(v.x - __low2float(h0), v.y - __high2float(h0));
            __nv_bfloat162 l1 = __floats2bfloat162_rn(v.z - __low2float(h1), v.w - __high2float(h1));
            *(u32*)(hib + i*8)     = *(u32*)&h0;
            *(u32*)(hib + i*8 + 4) = *(u32*)&h1;
            *(u32*)(lob + i*8)     = *(u32*)&l0;
            *(u32*)(lob + i*8 + 4) = *(u32*)&l1;
        }
        __syncthreads();

        for (int ks = 0; ks < 8; ++ks) {
            // B fragments for this k-step (L2-resident, warp-coalesced LDG.64)
            u32 bh[8][2], bl[8][2];
            const int ksa = c*8 + ks;
            #pragma unroll
            for (int nf = 0; nf < 8; ++nf) {
                const int idx = ((wn*8 + nf)*16 + ksa)*32 + lane;
                const u64 vh = WBH[idx], vl = WBL[idx];
                bh[nf][0] = (u32)vh; bh[nf][1] = (u32)(vh >> 32);
                bl[nf][0] = (u32)vl; bl[nf][1] = (u32)(vl >> 32);
            }
            #pragma unroll
            for (int mf = 0; mf < 4; ++mf) {
                const int ro = (arow + mf*16)*ASTRIDE + ks*32 + acol;
                const u32 ah0 = *(const u32*)(smem + SM_HI + ro);
                const u32 ah1 = *(const u32*)(smem + SM_HI + ro + 8*ASTRIDE);
                const u32 ah2 = *(const u32*)(smem + SM_HI + ro + 16);
                const u32 ah3 = *(const u32*)(smem + SM_HI + ro + 8*ASTRIDE + 16);
                const u32 al0 = *(const u32*)(smem + SM_LO + ro);
                const u32 al1 = *(const u32*)(smem + SM_LO + ro + 8*ASTRIDE);
                const u32 al2 = *(const u32*)(smem + SM_LO + ro + 16);
                const u32 al3 = *(const u32*)(smem + SM_LO + ro + 8*ASTRIDE + 16);
                #pragma unroll
                for (int nf = 0; nf < 8; ++nf) {
                    mma16816(acc[mf][nf], ah0, ah1, ah2, ah3, bh[nf][0], bh[nf][1]);
                    mma16816(acc[mf][nf], ah0, ah1, ah2, ah3, bl[nf][0], bl[nf][1]);
                    mma16816(acc[mf][nf], al0, al1, al2, al3, bh[nf][0], bh[nf][1]);
                }
            }
        }
    }

    // ---- store: d0,d1 -> (r, col..col+1), d2,d3 -> (r+8, col..col+1) ----
    const int rbase = m0 + wm*64 + (lane >> 2);
    const int cbase = wn*64 + (lane & 3)*2;
    #pragma unroll
    for (int mf = 0; mf < 4; ++mf) {
        const int r0 = rbase + mf*16;
        #pragma unroll
        for (int nf = 0; nf < 8; ++nf) {
            const int cc = cbase + nf*8;
            if (r0 < NN)
                *(float2*)(g_bufB + (size_t)r0*FD + cc) = make_float2(acc[mf][nf][0], acc[mf][nf][1]);
            if (r0 + 8 < NN)
                *(float2*)(g_bufB + (size_t)(r0+8)*FD + cc) = make_float2(acc[mf][nf][2], acc[mf][nf][3]);
        }
    }
}

// ============================================================
// Pass B: Z = A_hat @ Y + bias (per graph), accumulate BN sums.
// Buffers joint-major: row m = j*Bn + g.
// ============================================================
__global__ void __launch_bounds__(256)
sparse_kernel(const float* __restrict__ bias, int Bn) {
    __shared__ float sy[NJ*FD];
    __shared__ int   srp[NJ+1];
    __shared__ int   sci[MAXE];
    __shared__ float sav[MAXE];
    const int tid = threadIdx.x;
    const int g   = blockIdx.x;

    if (tid <= NJ) srp[tid] = g_rp[tid];
    if (tid < MAXE) { sci[tid] = g_ci[tid]; sav[tid] = g_av[tid]; }
    #pragma unroll
    for (int r = 0; r < NJ; ++r)
        sy[r*FD + tid] = g_bufB[((size_t)r*Bn + g)*FD + tid];
    __syncthreads();

    const float bf = bias[tid];
    float s1 = 0.f, s2 = 0.f;
    #pragma unroll 4
    for (int j = 0; j < NJ; ++j) {
        float z = bf;
        const int p1 = srp[j+1];
        for (int p = srp[j]; p < p1; ++p)
            z = fmaf(sav[p], sy[sci[p]*FD + tid], z);
        g_bufA[((size_t)j*Bn + g)*FD + tid] = z;
        s1 += z;
        s2 = fmaf(z, z, s2);
    }
    atomicAdd(&g_sum[tid], s1);
    atomicAdd(&g_sumsq[tid], s2);
}

// ============================================================
__global__ void stats_kernel(const float* __restrict__ g, const float* __restrict__ be,
                             float inv_nn) {
    int tid = threadIdx.x;
    float mu  = g_sum[tid] * inv_nn;
    float var = g_sumsq[tid] * inv_nn - mu * mu;
    float rs  = rsqrtf(var + 1e-5f);
    float sc  = rs * g[tid];
    g_scale[tid] = sc;
    g_shift[tid] = be[tid] - mu * sc;
    g_sum[tid] = 0.f; g_sumsq[tid] = 0.f;
}

// ============================================================
// Head: BN2+ReLU -> a_col^T h (per graph) -> @ (wh@wc) + bhc
// ============================================================
__global__ void __launch_bounds__(256)
final_kernel(float* __restrict__ out, int Bn) {
    __shared__ float s_acol[NJ];
    __shared__ float s_red[8][4];
    const int tid = threadIdx.x;
    const int b   = blockIdx.x;
    if (tid < NJ) s_acol[tid] = g_acol[tid];
    __syncthreads();

    const float sc  = g_scale[tid];
    const float shf = g_shift[tid];

    float v = 0.f;
    #pragma unroll
    for (int r = 0; r < NJ; ++r) {
        float x = g_bufA[((size_t)r*Bn + b)*FD + tid];
        x = fmaxf(fmaf(x, sc, shf), 0.f);
        v = fmaf(s_acol[r], x, v);
    }
    float4 w = ((const float4*)g_whc)[tid];
    float p0 = v * w.x, p1 = v * w.y, p2 = v * w.z, p3 = v * w.w;
    #pragma unroll
    for (int o = 16; o; o >>= 1) {
        p0 += __shfl_down_sync(0xffffffffu, p0, o);
        p1 += __shfl_down_sync(0xffffffffu, p1, o);
        p2 += __shfl_down_sync(0xffffffffu, p2, o);
        p3 += __shfl_down_sync(0xffffffffu, p3, o);
    }
    const int lane = tid & 31, wid = tid >> 5;
    if (lane == 0) { s_red[wid][0] = p0; s_red[wid][1] = p1; s_red[wid][2] = p2; s_red[wid][3] = p3; }
    __syncthreads();
    if (tid < 4) {
        float s = 0.f;
        #pragma unroll
        for (int w8 = 0; w8 < 8; ++w8) s += s_red[w8][tid];
        out[b*4 + tid] = s + g_bhc[tid];
    }
}

// ============================================================
extern "C" void kernel_launch(void* const* d_in, const int* in_sizes, int n_in,
                              void* d_out, int out_size) {
    const float* x   = (const float*)d_in[0];
    const float* w0  = (const float*)d_in[1];
    const float* b0  = (const float*)d_in[2];
    const float* gg0 = (const float*)d_in[3];
    const float* be0 = (const float*)d_in[4];
    const float* w1  = (const float*)d_in[5];
    const float* b1  = (const float*)d_in[6];
    const float* gg1 = (const float*)d_in[7];
    const float* be1 = (const float*)d_in[8];
    const float* w2  = (const float*)d_in[9];
    const float* b2  = (const float*)d_in[10];
    const float* gg2 = (const float*)d_in[11];
    const float* be2 = (const float*)d_in[12];
    const float* wh  = (const float*)d_in[13];
    const float* bh  = (const float*)d_in[14];
    const float* wc  = (const float*)d_in[15];
    const float* bc  = (const float*)d_in[16];
    const int*   src = (const int*)d_in[17];
    const int*   dst = (const int*)d_in[18];
    float* out = (float*)d_out;

    const int B   = in_sizes[0] / (NJ * FD);
    const int NN  = B * NJ;
    const int epg = in_sizes[17] / B;
    const float inv_nn = 1.0f / (float)NN;
    const int gemm_grid = (NN + 127) / 128;

    static int smem_set = 0;
    if (!smem_set) {
        cudaFuncSetAttribute(gemm_kernel, cudaFuncAttributeMaxDynamicSharedMemorySize, GEMM_SMEM);
        smem_set = 1;
    }

    prep_kernel<<<1, 256>>>(src, dst, epg, wh, wc, bh, bc);
    convw_kernel<<<64, 256>>>(w0, 0);
    convw_kernel<<<64, 256>>>(w1, 1);
    convw_kernel<<<64, 256>>>(w2, 2);

    gemm_kernel<<<gemm_grid, 256, GEMM_SMEM>>>(x, 0, 0, B, NN);
    sparse_kernel<<<B, 256>>>(b0, B);
    stats_kernel<<<1, 256>>>(gg0, be0, inv_nn);

    gemm_kernel<<<gemm_grid, 256, GEMM_SMEM>>>(nullptr, 1, 1, B, NN);
    sparse_kernel<<<B, 256>>>(b1, B);
    stats_kernel<<<1, 256>>>(gg1, be1, inv_nn);

    gemm_kernel<<<gemm_grid, 256, GEMM_SMEM>>>(nullptr, 1, 2, B, NN);
    sparse_kernel<<<B, 256>>>(b2, B);
    stats_kernel<<<1, 256>>>(gg2, be2, inv_nn);

    final_kernel<<<B, 256>>>(out, B);
}